// round 10
// baseline (speedup 1.0000x reference)
#include <cuda_runtime.h>

typedef unsigned long long u64;
typedef unsigned int u32;

// ---- packed f32x2 helpers (Blackwell sm_100a) ----
__device__ __forceinline__ u64 pk2(float lo, float hi) {
    u64 r; asm("mov.b64 %0, {%1, %2};" : "=l"(r) : "f"(lo), "f"(hi)); return r;
}
__device__ __forceinline__ void upk2(u64 v, float& lo, float& hi) {
    asm("mov.b64 {%0, %1}, %2;" : "=f"(lo), "=f"(hi) : "l"(v));
}
__device__ __forceinline__ u64 fma2(u64 a, u64 b, u64 c) {
    u64 r; asm("fma.rn.f32x2 %0, %1, %2, %3;" : "=l"(r) : "l"(a), "l"(b), "l"(c)); return r;
}
__device__ __forceinline__ u64 dup2(u32 m) {
    u64 r; asm("mov.b64 %0, {%1, %1};" : "=l"(r) : "r"(m)); return r;
}

// 10-qubit register: wire w = flat-index bit (9-w).
// 2 elements per warp; 16 lanes (l = lane&15) per element; 64 amps/thread.
// XOR-skewed storage: register r holds the amp whose local-slot bits are
//   y = r ^ (l & 15)   (bits 0..3 skewed by lane bits; bits 4,5 unskewed)
// Wire assignment alternates per layer (parity p):
//   p=0: lane slot u <-> global bit 6+u ; local slot v <-> global bit v
//   p=1: lane slot u <-> global bit u   ; local slot v<4 <-> bit 6+v ; slots 4,5 <-> bits 4,5
// Swap(lane j <-> local j) in this skew = plain shfl_xor(1<<j) on regs with bit j set.
// Gates on slot k commute with swaps on bit j!=k (the swap preserves lane
// bit k, so the gate's lane-dependent sign matches across the exchange):
// this lets every swap burst hide under a neighboring gate's 64 FMAs.

template<int J>
__device__ __forceinline__ void swap_bit(u64 (&st)[64]) {
#pragma unroll
    for (int r = 0; r < 64; r++)
        if (r & (1 << J))
            st[r] = __shfl_xor_sync(0xffffffffu, st[r], 1 << J);
}

template<int K>
__device__ __forceinline__ void gate_slot(u64 (&st)[64], u64 tt, u64 nt) {
#pragma unroll
    for (int w = 0; w < 32; w++) {
        const int i  = ((w >> K) << (K + 1)) | (w & ((1 << K) - 1));
        const int j2 = i | (1 << K);
        const u64 a0 = st[i], a1 = st[j2];
        st[i]  = fma2(nt, a1, a0);   // a0 - te*a1
        st[j2] = fma2(tt, a0, a1);   // a1 + te*a0
    }
}

__global__ __launch_bounds__(128, 3)
void qsim_kernel(const float* __restrict__ x,
                 const float* __restrict__ params,
                 const float* __restrict__ w_cls,
                 const float* __restrict__ b_cls,
                 float* __restrict__ out, int B)
{
    __shared__ float tsh[64], cwork[64], T2[64], wsh[160], bsh[16];
    __shared__ float Cprod_sh;
    const int tid = threadIdx.x;
    if (tid < 60) {
        float s, c;
        sincosf(params[tid] * 0.5f, &s, &c);
        tsh[tid] = s / c;          // tan(theta/2)
        cwork[tid] = c;
    }
    for (int k = tid; k < 160; k += 128) wsh[k] = w_cls[k];
    if (tid < 16) bsh[tid] = b_cls[tid];
    __syncthreads();
    // reorder thetas into per-layer gate order: k=0..5 phase-1 slots, k=6..9 phase-2 slots
    if (tid < 60) {
        int d = tid / 10, k = tid % 10, p = d & 1;
        int wire;
        if (k < 6) wire = p ? ((k < 4) ? 3 - k : 9 - k) : 9 - k;
        else { int j = k - 6; wire = p ? 9 - j : 3 - j; }
        T2[tid] = tsh[d * 10 + wire];
    }
    if (tid == 0) {
        float pp = 1.0f;
        for (int k = 0; k < 60; k++) pp *= cwork[k];
        Cprod_sh = pp;             // deferred cos product
    }
    __syncthreads();
    const float Cprod = Cprod_sh;

    const int lane = tid & 31;
    const int l    = lane & 15;
    const int half = lane >> 4;
    const int elem = (blockIdx.x * (blockDim.x >> 5) + (tid >> 5)) * 2 + half;
    if (elem >= B) return;

    // ---------- initial product state from RX layer (parity 0, skewed) ----------
    float cx[10], sx[10];
#pragma unroll
    for (int q = 0; q < 10; q++) {
        float xv = x[elem * 10 + q];
        sincosf(xv * 0.5f, &sx[q], &cx[q]);
    }
    // lane product: lane slot u <-> bit 6+u <-> wire 3-u
    float lp = Cprod;
#pragma unroll
    for (int u = 0; u < 4; u++)
        lp *= ((l >> u) & 1) ? sx[3 - u] : cx[3 - u];

    // skew-aware per-level factors: reg bit v=1 means amp bit y_v = 1^l_v (v<4)
    float fhi[6], flo[6];
#pragma unroll
    for (int v = 0; v < 4; v++) {
        const bool lb = (l >> v) & 1;
        fhi[v] = lb ? cx[9 - v] : sx[9 - v];
        flo[v] = lb ? sx[9 - v] : cx[9 - v];
    }
    fhi[4] = sx[5]; flo[4] = cx[5];
    fhi[5] = sx[4]; flo[5] = cx[4];

    float pr[64];
    pr[0] = lp;
#pragma unroll
    for (int v = 0; v < 6; v++) {
#pragma unroll
        for (int i = 0; i < 32; i++) {
            if (i < (1 << v)) {
                pr[i | (1 << v)] = pr[i] * fhi[v];
                pr[i]            = pr[i] * flo[v];
            }
        }
    }

    // phase (-i)^popc(b): parity of popc splits; 2E-term via per-thread bit table
    u32 Tpar = 0;
    if (l & 1) Tpar ^= 0xAAAAu;
    if (l & 2) Tpar ^= 0xCCCCu;
    if (l & 4) Tpar ^= 0xF0F0u;
    if (l & 8) Tpar ^= 0xFF00u;
    if (__popc(l) & 1) Tpar ^= 0xFFFFu;

    u64 st[64];
#pragma unroll
    for (int r = 0; r < 64; r++) {
        const int C = __popc(r);                       // compile-time
        const u32 e31 = ((Tpar >> (r & 15)) & 1u) << 31;
        const u32 bits = __float_as_uint(pr[r]);
        if ((C & 1) == 0) {
            const u32 reb = bits ^ e31 ^ ((u32)((C >> 1) & 1) << 31);
            st[r] = pk2(__uint_as_float(reb), 0.0f);
        } else {
            const u32 imb = bits ^ e31 ^ ((u32)(((C >> 1) & 1) ^ 1) << 31);
            st[r] = pk2(0.0f, __uint_as_float(imb));
        }
    }

    // ---------- CZ flip tables (16-bit words indexed by r&15) ----------
    u32 A = 0xB848u;
    if (l & 1) A = ((A & 0x5555u) << 1) | ((A & 0xAAAAu) >> 1);
    if (l & 2) A = ((A & 0x3333u) << 2) | ((A & 0xCCCCu) >> 2);
    if (l & 4) A = ((A & 0x0F0Fu) << 4) | ((A & 0xF0F0u) >> 4);
    if (l & 8) A = ((A & 0x00FFu) << 8) | ((A & 0xFF00u) >> 8);
    const u32 adjl = (__popc(l & (l >> 1)) & 1) ? 0xFFFFu : 0u;
    const u32 base = A ^ adjl;
    const u32 Y0 = (l & 1) ? 0x5555u : 0xAAAAu;   // r-bits where y0=1
    const u32 Y3 = (l & 8) ? 0x00FFu : 0xFF00u;   // r-bits where y3=1
    const u32 L3 = (l & 8) ? 0xFFFFu : 0u;
    const u32 L0 = (l & 1) ? 0xFFFFu : 0u;
    // parity-1 exit: flip = ADJ4(l) ^ l3*r4 ^ r4*r5 ^ r5*y0 ^ ADJ4(y)
    const u32 W1_00 = base;
    const u32 W1_10 = base ^ L3;
    const u32 W1_01 = base ^ Y0;
    const u32 W1_11 = base ^ L3 ^ 0xFFFFu ^ Y0;
    // parity-0 exit: flip = ADJ4(y) ^ y3*r4 ^ r4*r5 ^ r5*l0 ^ ADJ4(l)
    const u32 W0_00 = base;
    const u32 W0_10 = base ^ Y3;
    const u32 W0_01 = base ^ L0;
    const u32 W0_11 = base ^ Y3 ^ 0xFFFFu ^ L0;

    // ---------- 6 variational layers ----------
#pragma unroll 1
    for (int d = 0; d < 6; d++) {
        const int p = d & 1;

        // phase-1 coefficients (slots 0-3 skew-signed; 4,5 plain)
        u64 p1_tt[6], p1_nt[6];
#pragma unroll
        for (int k = 0; k < 6; k++) {
            const float t = T2[d * 10 + k];
            const float te = (k < 4 && ((l >> k) & 1)) ? -t : t;
            p1_tt[k] = pk2(te, te);
            p1_nt[k] = pk2(-te, -te);
        }
        // phase-2 coefficients (lane-sign-adjusted)
        u64 g_tt[4], g_nt[4];
#pragma unroll
        for (int k = 0; k < 4; k++) {
            const float t = T2[d * 10 + 6 + k];
            const float te = ((l >> k) & 1) ? -t : t;
            g_tt[k] = pk2(te, te);
            g_nt[k] = pk2(-te, -te);
        }

        // fully threaded schedule: every swap burst sits between gate bodies.
        gate_slot<0>(st, p1_tt[0], p1_nt[0]);
        gate_slot<1>(st, p1_tt[1], p1_nt[1]);
        gate_slot<2>(st, p1_tt[2], p1_nt[2]);
        gate_slot<3>(st, p1_tt[3], p1_nt[3]);
        swap_bit<0>(st);
        gate_slot<4>(st, p1_tt[4], p1_nt[4]);
        swap_bit<1>(st);
        gate_slot<5>(st, p1_tt[5], p1_nt[5]);
        swap_bit<2>(st);
        gate_slot<0>(st, g_tt[0], g_nt[0]);
        swap_bit<3>(st);
        gate_slot<1>(st, g_tt[1], g_nt[1]);
        gate_slot<2>(st, g_tt[2], g_nt[2]);
        gate_slot<3>(st, g_tt[3], g_nt[3]);

        // CZ chain (diagonal): sign-bit XOR from per-thread tables; skip last.
        // 4 regs share one shift amount (r15); & folds into the XOR LOP3.
        if (d < 5) {
            const int q = p ^ 1;   // exit parity
            const u32 Wa = q ? W1_00 : W0_00;
            const u32 Wb = q ? W1_10 : W0_10;
            const u32 Wc = q ? W1_01 : W0_01;
            const u32 Wd = q ? W1_11 : W0_11;
#pragma unroll
            for (int r15 = 0; r15 < 16; r15++) {
                const int sh = 31 - r15;
                st[r15]      ^= dup2((Wa << sh) & 0x80000000u);
                st[r15 + 16] ^= dup2((Wb << sh) & 0x80000000u);
                st[r15 + 32] ^= dup2((Wc << sh) & 0x80000000u);
                st[r15 + 48] ^= dup2((Wd << sh) & 0x80000000u);
            }
        }
    }

    // ---------- probabilities and <Z_q> (final layout = parity 0, skewed) ----------
    float t_all = 0.0f, tb[6] = {0, 0, 0, 0, 0, 0};
#pragma unroll
    for (int r = 0; r < 64; r++) {
        float re, im; upk2(st[r], re, im);
        const float p2 = fmaf(im, im, re * re);
        t_all += p2;
#pragma unroll
        for (int v = 0; v < 6; v++)
            if (r & (1 << v)) tb[v] += p2;
    }
    float ex[10];
#pragma unroll
    for (int q2 = 0; q2 < 4; q2++)                    // lane slots: bit 6+u -> wire 3-u
        ex[q2] = ((l >> (3 - q2)) & 1) ? -t_all : t_all;
#pragma unroll
    for (int v = 0; v < 4; v++) {                     // skewed local slots: bit v -> wire 9-v
        const float e = t_all - 2.0f * tb[v];
        ex[9 - v] = ((l >> v) & 1) ? -e : e;
    }
    ex[5] = t_all - 2.0f * tb[4];                     // bit 4 -> wire 5
    ex[4] = t_all - 2.0f * tb[5];                     // bit 5 -> wire 4

    // reduce across the 16 lanes of this element
#pragma unroll
    for (int m = 8; m >= 1; m >>= 1) {
#pragma unroll
        for (int q2 = 0; q2 < 10; q2++)
            ex[q2] += __shfl_xor_sync(0xffffffffu, ex[q2], m);
    }

    // ---------- classifier head: each of 16 lanes emits one class ----------
    {
        float acc = bsh[l];
#pragma unroll
        for (int q2 = 0; q2 < 10; q2++)
            acc = fmaf(ex[q2], wsh[l * 10 + q2], acc);
        out[elem * 16 + l] = acc;
    }
}

extern "C" void kernel_launch(void* const* d_in, const int* in_sizes, int n_in,
                              void* d_out, int out_size)
{
    const float* x      = (const float*)d_in[0];  // (B, 10)
    const float* params = (const float*)d_in[1];  // (6, 10)
    const float* w_cls  = (const float*)d_in[2];  // (16, 10)
    const float* b_cls  = (const float*)d_in[3];  // (16,)
    float* out = (float*)d_out;

    const int B = in_sizes[0] / 10;
    const int elems_per_block = 8;                // 4 warps x 2 elements
    const int blocks = (B + elems_per_block - 1) / elems_per_block;
    qsim_kernel<<<blocks, 128>>>(x, params, w_cls, b_cls, out, B);
}

// round 11
// speedup vs baseline: 1.0670x; 1.0670x over previous
#include <cuda_runtime.h>

typedef unsigned long long u64;
typedef unsigned int u32;

// ---- packed f32x2 helpers (Blackwell sm_100a) ----
__device__ __forceinline__ u64 pk2(float lo, float hi) {
    u64 r; asm("mov.b64 %0, {%1, %2};" : "=l"(r) : "f"(lo), "f"(hi)); return r;
}
__device__ __forceinline__ void upk2(u64 v, float& lo, float& hi) {
    asm("mov.b64 {%0, %1}, %2;" : "=f"(lo), "=f"(hi) : "l"(v));
}
__device__ __forceinline__ u64 fma2(u64 a, u64 b, u64 c) {
    u64 r; asm("fma.rn.f32x2 %0, %1, %2, %3;" : "=l"(r) : "l"(a), "l"(b), "l"(c)); return r;
}
__device__ __forceinline__ u64 dup2(u32 m) {
    u64 r; asm("mov.b64 %0, {%1, %1};" : "=l"(r) : "r"(m)); return r;
}

// 10-qubit register: wire w = flat-index bit (9-w).
// 2 elements per warp; 16 lanes (l = lane&15) per element; 64 amps/thread.
// XOR-skewed storage: register r holds the amp whose local-slot bits are
//   y = r ^ (l & 15)   (bits 0..3 skewed by lane bits; bits 4,5 unskewed)
// Wire assignment alternates per layer (parity p):
//   p=0: lane slot u <-> global bit 6+u ; local slot v <-> global bit v
//   p=1: lane slot u <-> global bit u   ; local slot v<4 <-> bit 6+v ; slots 4,5 <-> bits 4,5
// The full 4-bit lane<->local exchange fuses into ONE shuffle per register:
// the per-bit swaps (shfl_xor(1<<j) on regs with bit j set) compose to a net
// lane-XOR of (r & 15) for register r — a single shfl_xor with mask r&15.
// Gates on slots 4,5 have no lane-dependent sign and commute with the swap.

template<int K>
__device__ __forceinline__ void gate_slot(u64 (&st)[64], u64 tt, u64 nt) {
#pragma unroll
    for (int w = 0; w < 32; w++) {
        const int i  = ((w >> K) << (K + 1)) | (w & ((1 << K) - 1));
        const int j2 = i | (1 << K);
        const u64 a0 = st[i], a1 = st[j2];
        st[i]  = fma2(nt, a1, a0);   // a0 - te*a1
        st[j2] = fma2(tt, a0, a1);   // a1 + te*a0
    }
}

__global__ __launch_bounds__(128, 3)
void qsim_kernel(const float* __restrict__ x,
                 const float* __restrict__ params,
                 const float* __restrict__ w_cls,
                 const float* __restrict__ b_cls,
                 float* __restrict__ out, int B)
{
    __shared__ float tsh[64], cwork[64], T2[64], wsh[160], bsh[16];
    __shared__ float Cprod_sh;
    const int tid = threadIdx.x;
    if (tid < 60) {
        float s, c;
        sincosf(params[tid] * 0.5f, &s, &c);
        tsh[tid] = s / c;          // tan(theta/2)
        cwork[tid] = c;
    }
    for (int k = tid; k < 160; k += 128) wsh[k] = w_cls[k];
    if (tid < 16) bsh[tid] = b_cls[tid];
    __syncthreads();
    // reorder thetas into per-layer gate order: k=0..5 phase-1 slots, k=6..9 phase-2 slots
    if (tid < 60) {
        int d = tid / 10, k = tid % 10, p = d & 1;
        int wire;
        if (k < 6) wire = p ? ((k < 4) ? 3 - k : 9 - k) : 9 - k;
        else { int j = k - 6; wire = p ? 9 - j : 3 - j; }
        T2[tid] = tsh[d * 10 + wire];
    }
    if (tid == 0) {
        float pp = 1.0f;
        for (int k = 0; k < 60; k++) pp *= cwork[k];
        Cprod_sh = pp;             // deferred cos product
    }
    __syncthreads();
    const float Cprod = Cprod_sh;

    const int lane = tid & 31;
    const int l    = lane & 15;
    const int half = lane >> 4;
    const int elem = (blockIdx.x * (blockDim.x >> 5) + (tid >> 5)) * 2 + half;
    if (elem >= B) return;

    // ---------- initial product state from RX layer (parity 0, skewed) ----------
    float cx[10], sx[10];
#pragma unroll
    for (int q = 0; q < 10; q++) {
        float xv = x[elem * 10 + q];
        sincosf(xv * 0.5f, &sx[q], &cx[q]);
    }
    // lane product: lane slot u <-> bit 6+u <-> wire 3-u
    float lp = Cprod;
#pragma unroll
    for (int u = 0; u < 4; u++)
        lp *= ((l >> u) & 1) ? sx[3 - u] : cx[3 - u];

    // skew-aware per-level factors: reg bit v=1 means amp bit y_v = 1^l_v (v<4)
    float fhi[6], flo[6];
#pragma unroll
    for (int v = 0; v < 4; v++) {
        const bool lb = (l >> v) & 1;
        fhi[v] = lb ? cx[9 - v] : sx[9 - v];
        flo[v] = lb ? sx[9 - v] : cx[9 - v];
    }
    fhi[4] = sx[5]; flo[4] = cx[5];
    fhi[5] = sx[4]; flo[5] = cx[4];

    float pr[64];
    pr[0] = lp;
#pragma unroll
    for (int v = 0; v < 6; v++) {
#pragma unroll
        for (int i = 0; i < 32; i++) {
            if (i < (1 << v)) {
                pr[i | (1 << v)] = pr[i] * fhi[v];
                pr[i]            = pr[i] * flo[v];
            }
        }
    }

    // phase (-i)^popc(b): parity of popc splits; 2E-term via per-thread bit table
    u32 Tpar = 0;
    if (l & 1) Tpar ^= 0xAAAAu;
    if (l & 2) Tpar ^= 0xCCCCu;
    if (l & 4) Tpar ^= 0xF0F0u;
    if (l & 8) Tpar ^= 0xFF00u;
    if (__popc(l) & 1) Tpar ^= 0xFFFFu;

    u64 st[64];
#pragma unroll
    for (int r = 0; r < 64; r++) {
        const int C = __popc(r);                       // compile-time
        const u32 e31 = ((Tpar >> (r & 15)) & 1u) << 31;
        const u32 bits = __float_as_uint(pr[r]);
        if ((C & 1) == 0) {
            const u32 reb = bits ^ e31 ^ ((u32)((C >> 1) & 1) << 31);
            st[r] = pk2(__uint_as_float(reb), 0.0f);
        } else {
            const u32 imb = bits ^ e31 ^ ((u32)(((C >> 1) & 1) ^ 1) << 31);
            st[r] = pk2(0.0f, __uint_as_float(imb));
        }
    }

    // ---------- CZ flip tables (16-bit words indexed by r&15) ----------
    u32 A = 0xB848u;
    if (l & 1) A = ((A & 0x5555u) << 1) | ((A & 0xAAAAu) >> 1);
    if (l & 2) A = ((A & 0x3333u) << 2) | ((A & 0xCCCCu) >> 2);
    if (l & 4) A = ((A & 0x0F0Fu) << 4) | ((A & 0xF0F0u) >> 4);
    if (l & 8) A = ((A & 0x00FFu) << 8) | ((A & 0xFF00u) >> 8);
    const u32 adjl = (__popc(l & (l >> 1)) & 1) ? 0xFFFFu : 0u;
    const u32 base = A ^ adjl;
    const u32 Y0 = (l & 1) ? 0x5555u : 0xAAAAu;   // r-bits where y0=1
    const u32 Y3 = (l & 8) ? 0x00FFu : 0xFF00u;   // r-bits where y3=1
    const u32 L3 = (l & 8) ? 0xFFFFu : 0u;
    const u32 L0 = (l & 1) ? 0xFFFFu : 0u;
    // parity-1 exit: flip = ADJ4(l) ^ l3*r4 ^ r4*r5 ^ r5*y0 ^ ADJ4(y)
    const u32 W1_00 = base;
    const u32 W1_10 = base ^ L3;
    const u32 W1_01 = base ^ Y0;
    const u32 W1_11 = base ^ L3 ^ 0xFFFFu ^ Y0;
    // parity-0 exit: flip = ADJ4(y) ^ y3*r4 ^ r4*r5 ^ r5*l0 ^ ADJ4(l)
    const u32 W0_00 = base;
    const u32 W0_10 = base ^ Y3;
    const u32 W0_01 = base ^ L0;
    const u32 W0_11 = base ^ Y3 ^ 0xFFFFu ^ L0;

    // ---------- 6 variational layers ----------
#pragma unroll 1
    for (int d = 0; d < 6; d++) {
        const int p = d & 1;

        // phase-1 coefficients (slots 0-3 skew-signed; 4,5 plain)
        u64 p1_tt[6], p1_nt[6];
#pragma unroll
        for (int k = 0; k < 6; k++) {
            const float t = T2[d * 10 + k];
            const float te = (k < 4 && ((l >> k) & 1)) ? -t : t;
            p1_tt[k] = pk2(te, te);
            p1_nt[k] = pk2(-te, -te);
        }
        // phase-2 coefficients (lane-sign-adjusted)
        u64 g_tt[4], g_nt[4];
#pragma unroll
        for (int k = 0; k < 4; k++) {
            const float t = T2[d * 10 + 6 + k];
            const float te = ((l >> k) & 1) ? -t : t;
            g_tt[k] = pk2(te, te);
            g_nt[k] = pk2(-te, -te);
        }

        // phase-1 gates on all 6 local slots
        gate_slot<0>(st, p1_tt[0], p1_nt[0]);
        gate_slot<1>(st, p1_tt[1], p1_nt[1]);
        gate_slot<2>(st, p1_tt[2], p1_nt[2]);
        gate_slot<3>(st, p1_tt[3], p1_nt[3]);
        gate_slot<4>(st, p1_tt[4], p1_nt[4]);
        gate_slot<5>(st, p1_tt[5], p1_nt[5]);

        // FUSED lane<->local exchange: one shfl_xor per register, mask r&15.
        // (Composition of the four single-bit swaps; regs with r&15==0 stay.)
#pragma unroll
        for (int r = 0; r < 64; r++) {
            const int m = r & 15;
            if (m)
                st[r] = __shfl_xor_sync(0xffffffffu, st[r], m);
        }

        // phase-2 gates on the 4 wires that just arrived in local slots 0-3
        gate_slot<0>(st, g_tt[0], g_nt[0]);
        gate_slot<1>(st, g_tt[1], g_nt[1]);
        gate_slot<2>(st, g_tt[2], g_nt[2]);
        gate_slot<3>(st, g_tt[3], g_nt[3]);

        // CZ chain (diagonal): sign-bit XOR from per-thread tables; skip last.
        if (d < 5) {
            const int q = p ^ 1;   // exit parity
            const u32 Wa = q ? W1_00 : W0_00;
            const u32 Wb = q ? W1_10 : W0_10;
            const u32 Wc = q ? W1_01 : W0_01;
            const u32 Wd = q ? W1_11 : W0_11;
#pragma unroll
            for (int r15 = 0; r15 < 16; r15++) {
                const int sh = 31 - r15;
                st[r15]      ^= dup2((Wa << sh) & 0x80000000u);
                st[r15 + 16] ^= dup2((Wb << sh) & 0x80000000u);
                st[r15 + 32] ^= dup2((Wc << sh) & 0x80000000u);
                st[r15 + 48] ^= dup2((Wd << sh) & 0x80000000u);
            }
        }
    }

    // ---------- probabilities and <Z_q> (final layout = parity 0, skewed) ----------
    float t_all = 0.0f, tb[6] = {0, 0, 0, 0, 0, 0};
#pragma unroll
    for (int r = 0; r < 64; r++) {
        float re, im; upk2(st[r], re, im);
        const float p2 = fmaf(im, im, re * re);
        t_all += p2;
#pragma unroll
        for (int v = 0; v < 6; v++)
            if (r & (1 << v)) tb[v] += p2;
    }
    float ex[10];
#pragma unroll
    for (int q2 = 0; q2 < 4; q2++)                    // lane slots: bit 6+u -> wire 3-u
        ex[q2] = ((l >> (3 - q2)) & 1) ? -t_all : t_all;
#pragma unroll
    for (int v = 0; v < 4; v++) {                     // skewed local slots: bit v -> wire 9-v
        const float e = t_all - 2.0f * tb[v];
        ex[9 - v] = ((l >> v) & 1) ? -e : e;
    }
    ex[5] = t_all - 2.0f * tb[4];                     // bit 4 -> wire 5
    ex[4] = t_all - 2.0f * tb[5];                     // bit 5 -> wire 4

    // reduce across the 16 lanes of this element
#pragma unroll
    for (int m = 8; m >= 1; m >>= 1) {
#pragma unroll
        for (int q2 = 0; q2 < 10; q2++)
            ex[q2] += __shfl_xor_sync(0xffffffffu, ex[q2], m);
    }

    // ---------- classifier head: each of 16 lanes emits one class ----------
    {
        float acc = bsh[l];
#pragma unroll
        for (int q2 = 0; q2 < 10; q2++)
            acc = fmaf(ex[q2], wsh[l * 10 + q2], acc);
        out[elem * 16 + l] = acc;
    }
}

extern "C" void kernel_launch(void* const* d_in, const int* in_sizes, int n_in,
                              void* d_out, int out_size)
{
    const float* x      = (const float*)d_in[0];  // (B, 10)
    const float* params = (const float*)d_in[1];  // (6, 10)
    const float* w_cls  = (const float*)d_in[2];  // (16, 10)
    const float* b_cls  = (const float*)d_in[3];  // (16,)
    float* out = (float*)d_out;

    const int B = in_sizes[0] / 10;
    const int elems_per_block = 8;                // 4 warps x 2 elements
    const int blocks = (B + elems_per_block - 1) / elems_per_block;
    qsim_kernel<<<blocks, 128>>>(x, params, w_cls, b_cls, out, B);
}

// round 12
// speedup vs baseline: 1.3048x; 1.2228x over previous
#include <cuda_runtime.h>

typedef unsigned long long u64;
typedef unsigned int u32;

// ---- packed f32x2 helpers (Blackwell sm_100a) ----
__device__ __forceinline__ u64 pk2(float lo, float hi) {
    u64 r; asm("mov.b64 %0, {%1, %2};" : "=l"(r) : "f"(lo), "f"(hi)); return r;
}
__device__ __forceinline__ void upk2(u64 v, float& lo, float& hi) {
    asm("mov.b64 {%0, %1}, %2;" : "=f"(lo), "=f"(hi) : "l"(v));
}
__device__ __forceinline__ u64 fma2(u64 a, u64 b, u64 c) {
    u64 r; asm("fma.rn.f32x2 %0, %1, %2, %3;" : "=l"(r) : "l"(a), "l"(b), "l"(c)); return r;
}

#define PC6(v) ((((v)>>0)&1)+(((v)>>1)&1)+(((v)>>2)&1)+(((v)>>3)&1)+(((v)>>4)&1)+(((v)>>5)&1))

// 10-qubit register: wire w = flat-index bit (9-w).
// 2 elements per warp; 16 lanes (l = lane&15) per element; 64 amps/thread.
// XOR-skewed storage: register r holds the amp whose local-slot bits are
//   y = r ^ (l & 15)   (bits 0..3 skewed by lane bits; bits 4,5 unskewed)
// Wire assignment alternates per layer (parity p = d&1):
//   p=0: lane slot u <-> global bit 6+u ; local slot v <-> global bit v
//   p=1: lane slot u <-> global bit u   ; local slot v<4 <-> bit 6+v ; slots 4,5 <-> bits 4,5
// The 4-bit lane<->local exchange is ONE shfl_xor per register (mask r&15).
//
// CZ ELIMINATION BY CONJUGATION: CZ = diag sign D. For a tangent-form Givens
// pair, D G D^-1 = G with te -> sign(i)*sign(j)*te (diagonal is 1). Pushing
// D0 through layer 1 annihilates D1 (same sigma, D^2=I); D2 through layer 3
// kills D3; D4 through layer 5 dies against |amp|^2. So even layers run
// plain; ODD layers run with per-pair te signs:
//   gate on global bit t: sigma_i*sigma_j = (-1)^(b_{t-1} xor b_{t+1})
// which splits into a compile-time register-bit parity (RMASK, selects tt/nt
// per unrolled pair) and a lane-bit parity (folded into te's sign bit).

template<int K>
__device__ __forceinline__ void gate_slot(u64 (&st)[64], u64 tt, u64 nt) {
#pragma unroll
    for (int w = 0; w < 32; w++) {
        const int i  = ((w >> K) << (K + 1)) | (w & ((1 << K) - 1));
        const int j2 = i | (1 << K);
        const u64 a0 = st[i], a1 = st[j2];
        st[i]  = fma2(nt, a1, a0);   // a0 - te*a1
        st[j2] = fma2(tt, a0, a1);   // a1 + te*a0
    }
}

template<int K, int RMASK>
__device__ __forceinline__ void gate_slot_sig(u64 (&st)[64], u64 tt, u64 nt) {
#pragma unroll
    for (int w = 0; w < 32; w++) {
        const int i  = ((w >> K) << (K + 1)) | (w & ((1 << K) - 1));
        const int j2 = i | (1 << K);
        const int neg = PC6(i & RMASK) & 1;            // compile-time
        const u64 a0 = st[i], a1 = st[j2];
        if (neg) {
            st[i]  = fma2(tt, a1, a0);   // a0 + te*a1  (te negated)
            st[j2] = fma2(nt, a0, a1);   // a1 - te*a0
        } else {
            st[i]  = fma2(nt, a1, a0);
            st[j2] = fma2(tt, a0, a1);
        }
    }
}

__device__ __forceinline__ void swap_fused(u64 (&st)[64]) {
#pragma unroll
    for (int r = 0; r < 64; r++) {
        const int m = r & 15;
        if (m)
            st[r] = __shfl_xor_sync(0xffffffffu, st[r], m);
    }
}

__global__ __launch_bounds__(128, 3)
void qsim_kernel(const float* __restrict__ x,
                 const float* __restrict__ params,
                 const float* __restrict__ w_cls,
                 const float* __restrict__ b_cls,
                 float* __restrict__ out, int B)
{
    __shared__ float tsh[64], cwork[64], T2[64], wsh[160], bsh[16];
    __shared__ float Cprod_sh;
    const int tid = threadIdx.x;
    if (tid < 60) {
        float s, c;
        sincosf(params[tid] * 0.5f, &s, &c);
        tsh[tid] = s / c;          // tan(theta/2)
        cwork[tid] = c;
    }
    for (int k = tid; k < 160; k += 128) wsh[k] = w_cls[k];
    if (tid < 16) bsh[tid] = b_cls[tid];
    __syncthreads();
    // reorder thetas into per-layer gate order: k=0..5 phase-1 slots, k=6..9 phase-2 slots
    if (tid < 60) {
        int d = tid / 10, k = tid % 10, p = d & 1;
        int wire;
        if (k < 6) wire = p ? ((k < 4) ? 3 - k : 9 - k) : 9 - k;
        else { int j = k - 6; wire = p ? 9 - j : 3 - j; }
        T2[tid] = tsh[d * 10 + wire];
    }
    if (tid == 0) {
        float pp = 1.0f;
        for (int k = 0; k < 60; k++) pp *= cwork[k];
        Cprod_sh = pp;             // deferred cos product
    }
    __syncthreads();
    const float Cprod = Cprod_sh;

    const int lane = tid & 31;
    const int l    = lane & 15;
    const int half = lane >> 4;
    const int elem = (blockIdx.x * (blockDim.x >> 5) + (tid >> 5)) * 2 + half;
    if (elem >= B) return;

    // ---------- initial product state from RX layer (parity 0, skewed) ----------
    // lanes 0..9 of each half compute one sincos; broadcast packed (c,s).
    u64 cspack = 0;
    if (l < 10) {
        float s, c;
        sincosf(x[elem * 10 + l] * 0.5f, &s, &c);
        cspack = pk2(c, s);
    }
    float cx[10], sx[10];
#pragma unroll
    for (int q = 0; q < 10; q++) {
        u64 v = __shfl_sync(0xffffffffu, cspack, (lane & 16) + q);
        upk2(v, cx[q], sx[q]);
    }

    // lane product: lane slot u <-> bit 6+u <-> wire 3-u
    float lp = Cprod;
#pragma unroll
    for (int u = 0; u < 4; u++)
        lp *= ((l >> u) & 1) ? sx[3 - u] : cx[3 - u];

    // skew-aware per-level factors: reg bit v=1 means amp bit y_v = 1^l_v (v<4)
    float fhi[6], flo[6];
#pragma unroll
    for (int v = 0; v < 4; v++) {
        const bool lb = (l >> v) & 1;
        fhi[v] = lb ? cx[9 - v] : sx[9 - v];
        flo[v] = lb ? sx[9 - v] : cx[9 - v];
    }
    fhi[4] = sx[5]; flo[4] = cx[5];
    fhi[5] = sx[4]; flo[5] = cx[4];

    float pr[64];
    pr[0] = lp;
#pragma unroll
    for (int v = 0; v < 6; v++) {
#pragma unroll
        for (int i = 0; i < 32; i++) {
            if (i < (1 << v)) {
                pr[i | (1 << v)] = pr[i] * fhi[v];
                pr[i]            = pr[i] * flo[v];
            }
        }
    }

    // phase (-i)^popc(b): parity of popc splits; 2E-term via per-thread bit table
    u32 Tpar = 0;
    if (l & 1) Tpar ^= 0xAAAAu;
    if (l & 2) Tpar ^= 0xCCCCu;
    if (l & 4) Tpar ^= 0xF0F0u;
    if (l & 8) Tpar ^= 0xFF00u;
    if (__popc(l) & 1) Tpar ^= 0xFFFFu;

    u64 st[64];
#pragma unroll
    for (int r = 0; r < 64; r++) {
        const int C = PC6(r);                          // compile-time
        const u32 e31 = ((Tpar >> (r & 15)) & 1u) << 31;
        const u32 bits = __float_as_uint(pr[r]);
        if ((C & 1) == 0) {
            const u32 reb = bits ^ e31 ^ ((u32)((C >> 1) & 1) << 31);
            st[r] = pk2(__uint_as_float(reb), 0.0f);
        } else {
            const u32 imb = bits ^ e31 ^ ((u32)(((C >> 1) & 1) ^ 1) << 31);
            st[r] = pk2(0.0f, __uint_as_float(imb));
        }
    }

    // ---------- lane-dependent sign masks (float sign-bit XOR) ----------
    const u32 l0 = (l >> 0) & 1, l1 = (l >> 1) & 1, l2 = (l >> 2) & 1, l3 = (l >> 3) & 1;
    const u32 SGE[4] = { l0 << 31, l1 << 31, l2 << 31, l3 << 31 };   // even layers (skew only)
    // odd layers: skew sign ^ lane part of (b_{t-1} xor b_{t+1})
    const u32 SA = (l0 ^ l1) << 31;        // slots 0 (both phases)
    const u32 SB = (l0 ^ l1 ^ l2) << 31;   // slots 1
    const u32 SC = (l1 ^ l2 ^ l3) << 31;   // slots 2
    const u32 SD = (l2 ^ l3) << 31;        // slots 3
    const u32 S4 = l3 << 31;               // phase-1 slot 4
    const u32 S5 = l0 << 31;               // phase-1 slot 5

#define MKCOEF(tval_bits, sgn, TT, NT) do { \
        const float _te = __uint_as_float((tval_bits) ^ (sgn)); \
        TT = pk2(_te, _te); NT = pk2(-_te, -_te); } while (0)

    // ---------- 6 variational layers (CZ folded into odd-layer signs) ----------
#pragma unroll 1
    for (int dd = 0; dd < 3; dd++) {
        const float* Te = T2 + (2 * dd) * 10;
        const float* To = T2 + (2 * dd + 1) * 10;
        u64 tt, nt;

        // ======== even layer 2*dd (plain signs) ========
        MKCOEF(__float_as_uint(Te[0]), SGE[0], tt, nt); gate_slot<0>(st, tt, nt);
        MKCOEF(__float_as_uint(Te[1]), SGE[1], tt, nt); gate_slot<1>(st, tt, nt);
        MKCOEF(__float_as_uint(Te[2]), SGE[2], tt, nt); gate_slot<2>(st, tt, nt);
        MKCOEF(__float_as_uint(Te[3]), SGE[3], tt, nt); gate_slot<3>(st, tt, nt);
        MKCOEF(__float_as_uint(Te[4]), 0u,     tt, nt); gate_slot<4>(st, tt, nt);
        MKCOEF(__float_as_uint(Te[5]), 0u,     tt, nt); gate_slot<5>(st, tt, nt);
        swap_fused(st);
        MKCOEF(__float_as_uint(Te[6]), SGE[0], tt, nt); gate_slot<0>(st, tt, nt);
        MKCOEF(__float_as_uint(Te[7]), SGE[1], tt, nt); gate_slot<1>(st, tt, nt);
        MKCOEF(__float_as_uint(Te[8]), SGE[2], tt, nt); gate_slot<2>(st, tt, nt);
        MKCOEF(__float_as_uint(Te[9]), SGE[3], tt, nt); gate_slot<3>(st, tt, nt);

        // ======== odd layer 2*dd+1 (CZ-conjugated signs) ========
        // phase 1 (p=1 layout): slot k gates global bit 6+k (k<4), bits 4,5 (slots 4,5)
        MKCOEF(__float_as_uint(To[0]), SA, tt, nt); gate_slot_sig<0, 0x22>(st, tt, nt); // b5^b7: r5^r1
        MKCOEF(__float_as_uint(To[1]), SB, tt, nt); gate_slot_sig<1, 0x05>(st, tt, nt); // b6^b8: r0^r2
        MKCOEF(__float_as_uint(To[2]), SC, tt, nt); gate_slot_sig<2, 0x0A>(st, tt, nt); // b7^b9: r1^r3
        MKCOEF(__float_as_uint(To[3]), SD, tt, nt); gate_slot_sig<3, 0x04>(st, tt, nt); // b8   : r2
        MKCOEF(__float_as_uint(To[4]), S4, tt, nt); gate_slot_sig<4, 0x20>(st, tt, nt); // b3^b5: r5 (l3)
        MKCOEF(__float_as_uint(To[5]), S5, tt, nt); gate_slot_sig<5, 0x11>(st, tt, nt); // b4^b6: r4^r0 (l0)
        swap_fused(st);
        // phase 2 (p=0 layout): slot k gates global bit k
        MKCOEF(__float_as_uint(To[6]), SA, tt, nt); gate_slot_sig<0, 0x02>(st, tt, nt); // b1   : r1
        MKCOEF(__float_as_uint(To[7]), SB, tt, nt); gate_slot_sig<1, 0x05>(st, tt, nt); // b0^b2: r0^r2
        MKCOEF(__float_as_uint(To[8]), SC, tt, nt); gate_slot_sig<2, 0x0A>(st, tt, nt); // b1^b3: r1^r3
        MKCOEF(__float_as_uint(To[9]), SD, tt, nt); gate_slot_sig<3, 0x14>(st, tt, nt); // b2^b4: r2^r4
    }
#undef MKCOEF

    // ---------- probabilities and <Z_q> (final layout = parity 0, skewed) ----------
    float t_all = 0.0f, tb[6] = {0, 0, 0, 0, 0, 0};
#pragma unroll
    for (int r = 0; r < 64; r++) {
        float re, im; upk2(st[r], re, im);
        const float p2 = fmaf(im, im, re * re);
        t_all += p2;
#pragma unroll
        for (int v = 0; v < 6; v++)
            if (r & (1 << v)) tb[v] += p2;
    }
    float ex[10];
#pragma unroll
    for (int q2 = 0; q2 < 4; q2++)                    // lane slots: bit 6+u -> wire 3-u
        ex[q2] = ((l >> (3 - q2)) & 1) ? -t_all : t_all;
#pragma unroll
    for (int v = 0; v < 4; v++) {                     // skewed local slots: bit v -> wire 9-v
        const float e = t_all - 2.0f * tb[v];
        ex[9 - v] = ((l >> v) & 1) ? -e : e;
    }
    ex[5] = t_all - 2.0f * tb[4];                     // bit 4 -> wire 5
    ex[4] = t_all - 2.0f * tb[5];                     // bit 5 -> wire 4

    // reduce across the 16 lanes of this element
#pragma unroll
    for (int m = 8; m >= 1; m >>= 1) {
#pragma unroll
        for (int q2 = 0; q2 < 10; q2++)
            ex[q2] += __shfl_xor_sync(0xffffffffu, ex[q2], m);
    }

    // ---------- classifier head: each of 16 lanes emits one class ----------
    {
        float acc = bsh[l];
#pragma unroll
        for (int q2 = 0; q2 < 10; q2++)
            acc = fmaf(ex[q2], wsh[l * 10 + q2], acc);
        out[elem * 16 + l] = acc;
    }
}

extern "C" void kernel_launch(void* const* d_in, const int* in_sizes, int n_in,
                              void* d_out, int out_size)
{
    const float* x      = (const float*)d_in[0];  // (B, 10)
    const float* params = (const float*)d_in[1];  // (6, 10)
    const float* w_cls  = (const float*)d_in[2];  // (16, 10)
    const float* b_cls  = (const float*)d_in[3];  // (16,)
    float* out = (float*)d_out;

    const int B = in_sizes[0] / 10;
    const int elems_per_block = 8;                // 4 warps x 2 elements
    const int blocks = (B + elems_per_block - 1) / elems_per_block;
    qsim_kernel<<<blocks, 128>>>(x, params, w_cls, b_cls, out, B);
}